// round 4
// baseline (speedup 1.0000x reference)
#include <cuda_runtime.h>
#include <cstdint>

#define Nn 50000
#define Ee 800000
#define Fd 128          // feature dim = H*OUT = 128
#define NH 2            // heads

// ---------------- scratch (no allocations allowed) ----------------
__device__ float g_f[(size_t)Nn * Fd];    // projected feats for current relation
__device__ float g_agg[(size_t)Nn * Fd];  // unnormalized aggregation
__device__ float g_h1[(size_t)Nn * Fd];   // layer-1 output
__device__ float g_el[(size_t)Nn * NH];
__device__ float g_er[(size_t)Nn * NH];
__device__ float g_s[(size_t)Nn * NH];    // softmax denominators

// ---------------- packed f32x2 helpers (Blackwell FFMA2 path) ----------------
__device__ __forceinline__ unsigned long long pack2(float lo, float hi) {
    unsigned long long r;
    asm("mov.b64 %0, {%1, %2};" : "=l"(r) : "f"(lo), "f"(hi));
    return r;
}
__device__ __forceinline__ void fma2(unsigned long long& d, unsigned long long a,
                                     unsigned long long b) {
    asm("fma.rn.f32x2 %0, %1, %2, %0;" : "+l"(d) : "l"(a), "l"(b));
}
__device__ __forceinline__ float2 unpack2(unsigned long long v) {
    float2 r;
    asm("mov.b64 {%0, %1}, %2;" : "=f"(r.x), "=f"(r.y) : "l"(v));
    return r;
}

// ---------------- GEMM: C[nrows,128] = A[nrows,128] @ B[128,128] ----------------
// 128x128 tile per block, 256 threads, thread tile 8 rows x (4 + 4 split) cols,
// accumulation in packed f32x2.
#define GEMM_SMEM (128 * 132 * 4 + 128 * 128 * 4)

__global__ void __launch_bounds__(256) gemm_k(const float* __restrict__ A,
                                              const float* __restrict__ B,
                                              float* __restrict__ C, int nrows) {
    extern __shared__ float sm[];
    float* As = sm;               // [128][132] padded
    float* Bs = sm + 128 * 132;   // [128][128]
    const int m0 = blockIdx.x * 128;
    const int tid = threadIdx.x;

#pragma unroll
    for (int it = 0; it < 16; it++) {
        int idx = tid + it * 256;       // float4 index, 0..4095
        int row = idx >> 5;
        int c4 = (idx & 31) << 2;
        float4 va = make_float4(0.f, 0.f, 0.f, 0.f);
        if (m0 + row < nrows) va = *(const float4*)&A[(size_t)(m0 + row) * Fd + c4];
        *(float4*)&As[row * 132 + c4] = va;
        *(float4*)&Bs[row * 128 + c4] = *(const float4*)&B[row * Fd + c4];
    }
    __syncthreads();

    const int ty = tid >> 4;   // 0..15 -> rows ty*8..ty*8+7
    const int tx = tid & 15;   // cols tx*4..tx*4+3 and 64+tx*4..64+tx*4+3

    unsigned long long acc[8][4];
#pragma unroll
    for (int i = 0; i < 8; i++)
#pragma unroll
        for (int j = 0; j < 4; j++) acc[i][j] = 0ull;

#pragma unroll 4
    for (int k = 0; k < 128; k++) {
        float4 b0 = *(const float4*)&Bs[k * 128 + tx * 4];
        float4 b1 = *(const float4*)&Bs[k * 128 + 64 + tx * 4];
        unsigned long long bp0 = pack2(b0.x, b0.y);
        unsigned long long bp1 = pack2(b0.z, b0.w);
        unsigned long long bp2 = pack2(b1.x, b1.y);
        unsigned long long bp3 = pack2(b1.z, b1.w);
#pragma unroll
        for (int i = 0; i < 8; i++) {
            float a = As[(ty * 8 + i) * 132 + k];
            unsigned long long ap = pack2(a, a);
            fma2(acc[i][0], ap, bp0);
            fma2(acc[i][1], ap, bp1);
            fma2(acc[i][2], ap, bp2);
            fma2(acc[i][3], ap, bp3);
        }
    }

#pragma unroll
    for (int i = 0; i < 8; i++) {
        int row = m0 + ty * 8 + i;
        if (row < nrows) {
            float2 v0 = unpack2(acc[i][0]);
            float2 v1 = unpack2(acc[i][1]);
            float2 v2 = unpack2(acc[i][2]);
            float2 v3 = unpack2(acc[i][3]);
            *(float4*)&C[(size_t)row * Fd + tx * 4] = make_float4(v0.x, v0.y, v1.x, v1.y);
            *(float4*)&C[(size_t)row * Fd + 64 + tx * 4] = make_float4(v2.x, v2.y, v3.x, v3.y);
        }
    }
}

// ---------------- per-node attention scores: el/er[n,h] = dot(f[n,h,:], al/ar[h,:]) ----------------
__global__ void __launch_bounds__(256) scores_k(const float* __restrict__ f,
                                                const float* __restrict__ al,
                                                const float* __restrict__ ar,
                                                float* __restrict__ el,
                                                float* __restrict__ er) {
    int w = (int)(((size_t)blockIdx.x * blockDim.x + threadIdx.x) >> 5);
    if (w >= Nn) return;
    int lane = threadIdx.x & 31;
    float4 fv = *(const float4*)&f[(size_t)w * Fd + lane * 4];
    float4 av = *(const float4*)&al[lane * 4];
    float4 rv = *(const float4*)&ar[lane * 4];
    float pel = fv.x * av.x + fv.y * av.y + fv.z * av.z + fv.w * av.w;
    float per = fv.x * rv.x + fv.y * rv.y + fv.z * rv.z + fv.w * rv.w;
#pragma unroll
    for (int off = 8; off; off >>= 1) {
        pel += __shfl_down_sync(0xffffffffu, pel, off, 16);
        per += __shfl_down_sync(0xffffffffu, per, off, 16);
    }
    if ((lane & 15) == 0) {
        int h = lane >> 4;
        el[w * NH + h] = pel;
        er[w * NH + h] = per;
    }
}

// ---------------- edge pass: one warp per edge ----------------
// Softmax shift-invariance => skip segment-max (scores are O(1), no overflow).
// Normalization factors out => accumulate unnormalized: agg[dst] += f[src]*exp(e),
// s[dst] += exp(e). Vector RED (no return) for the 128-float scatter.
__global__ void __launch_bounds__(256) edge_k(const int* __restrict__ src,
                                              const int* __restrict__ dst,
                                              const float* __restrict__ el,
                                              const float* __restrict__ er,
                                              const float* __restrict__ f,
                                              float* __restrict__ agg,
                                              float* __restrict__ s) {
    long long gw = ((long long)blockIdx.x * blockDim.x + threadIdx.x) >> 5;
    if (gw >= Ee) return;
    int lane = threadIdx.x & 31;
    int u = __ldg(&src[gw]);
    int v = __ldg(&dst[gw]);
    int h = lane >> 4;
    float e = __ldg(&el[u * NH + h]) + __ldg(&er[v * NH + h]);
    e = (e > 0.f) ? e : 0.2f * e;           // leaky_relu(0.2)
    float w = __expf(e);
    if ((lane & 15) == 0) atomicAdd(&s[v * NH + h], w);
    float4 fv = *(const float4*)&f[(size_t)u * Fd + lane * 4];
    float* p = &agg[(size_t)v * Fd + lane * 4];
    asm volatile("red.global.add.v4.f32 [%0], {%1, %2, %3, %4};" ::"l"(p),
                 "f"(fv.x * w), "f"(fv.y * w), "f"(fv.z * w), "f"(fv.w * w)
                 : "memory");
}

// ---------------- epilogue: hout += elu(agg/s + b) ----------------
__global__ void __launch_bounds__(256) epi_k(const float* __restrict__ agg,
                                             const float* __restrict__ s,
                                             const float* __restrict__ b,
                                             float* __restrict__ hout) {
    int i = blockIdx.x * blockDim.x + threadIdx.x;
    if (i >= Nn * Fd) return;
    int n = i >> 7;
    int c = i & 127;
    int h = c >> 6;
    float sv = s[n * NH + h];
    float v = (sv > 0.f) ? agg[i] / sv : 0.f;  // nodes w/o in-edges: agg term is 0
    v += b[c];
    hout[i] += (v > 0.f) ? v : expm1f(v);      // elu, alpha=1
}

// ---------------- layer driver ----------------
static void run_layer(const float* hin, const float* W, const float* al,
                      const float* ar, const float* b, const int* src,
                      const int* dst, float* hout, float* f, float* agg,
                      float* el, float* er, float* s) {
    cudaMemsetAsync(hout, 0, (size_t)Nn * Fd * sizeof(float));
    for (int r = 0; r < 2; r++) {
        gemm_k<<<(Nn + 127) / 128, 256, GEMM_SMEM>>>(hin, W + (size_t)r * Fd * Fd, f, Nn);
        scores_k<<<(Nn * 32 + 255) / 256, 256>>>(f, al + r * Fd, ar + r * Fd, el, er);
        cudaMemsetAsync(agg, 0, (size_t)Nn * Fd * sizeof(float));
        cudaMemsetAsync(s, 0, (size_t)Nn * NH * sizeof(float));
        edge_k<<<(int)(((long long)Ee * 32) / 256), 256>>>(
            src + (size_t)r * Ee, dst + (size_t)r * Ee, el, er, f, agg, s);
        epi_k<<<(Nn * Fd + 255) / 256, 256>>>(agg, s, b + r * Fd, hout);
    }
}

extern "C" void kernel_launch(void* const* d_in, const int* in_sizes, int n_in,
                              void* d_out, int out_size) {
    const float* x   = (const float*)d_in[0];
    const float* W0  = (const float*)d_in[1];
    const float* al0 = (const float*)d_in[2];
    const float* ar0 = (const float*)d_in[3];
    const float* b0  = (const float*)d_in[4];
    const float* W1  = (const float*)d_in[5];
    const float* al1 = (const float*)d_in[6];
    const float* ar1 = (const float*)d_in[7];
    const float* b1  = (const float*)d_in[8];
    const int* src0  = (const int*)d_in[9];
    const int* dst0  = (const int*)d_in[10];
    const int* src1  = (const int*)d_in[11];
    const int* dst1  = (const int*)d_in[12];
    float* out = (float*)d_out;

    float *f, *agg, *h1, *el, *er, *s;
    cudaGetSymbolAddress((void**)&f, g_f);
    cudaGetSymbolAddress((void**)&agg, g_agg);
    cudaGetSymbolAddress((void**)&h1, g_h1);
    cudaGetSymbolAddress((void**)&el, g_el);
    cudaGetSymbolAddress((void**)&er, g_er);
    cudaGetSymbolAddress((void**)&s, g_s);

    cudaFuncSetAttribute(gemm_k, cudaFuncAttributeMaxDynamicSharedMemorySize,
                         GEMM_SMEM);

    run_layer(x, W0, al0, ar0, b0, src0, dst0, h1, f, agg, el, er, s);
    run_layer(h1, W1, al1, ar1, b1, src1, dst1, out, f, agg, el, er, s);
}

// round 5
// speedup vs baseline: 1.0023x; 1.0023x over previous
#include <cuda_runtime.h>
#include <cstdint>

#define Nn 50000
#define Ee 800000
#define Fd 128          // feature dim = H*OUT = 128
#define NH 2            // heads

// ---------------- scratch (no allocations allowed) ----------------
__device__ float g_f[(size_t)Nn * Fd];    // projected feats for current relation
__device__ float g_agg[(size_t)Nn * Fd];  // unnormalized aggregation
__device__ float g_h1[(size_t)Nn * Fd];   // layer-1 output
__device__ float g_el[(size_t)Nn * NH];
__device__ float g_er[(size_t)Nn * NH];
__device__ float g_s[(size_t)Nn * NH];    // softmax denominators

// ---------------- packed f32x2 helpers (Blackwell FFMA2 path) ----------------
__device__ __forceinline__ unsigned long long pack2(float lo, float hi) {
    unsigned long long r;
    asm("mov.b64 %0, {%1, %2};" : "=l"(r) : "f"(lo), "f"(hi));
    return r;
}
__device__ __forceinline__ void fma2(unsigned long long& d, unsigned long long a,
                                     unsigned long long b) {
    asm("fma.rn.f32x2 %0, %1, %2, %0;" : "+l"(d) : "l"(a), "l"(b));
}
__device__ __forceinline__ float2 unpack2(unsigned long long v) {
    float2 r;
    asm("mov.b64 {%0, %1}, %2;" : "=f"(r.x), "=f"(r.y) : "l"(v));
    return r;
}

// ---------------- GEMM: C[nrows,128] = A[nrows,128] @ B[128,128] ----------------
// 128x128 tile per block, 256 threads, thread tile 8 rows x (4 + 4 split) cols,
// accumulation in packed f32x2.
#define GEMM_SMEM (128 * 132 * 4 + 128 * 128 * 4)

__global__ void __launch_bounds__(256) gemm_k(const float* __restrict__ A,
                                              const float* __restrict__ B,
                                              float* __restrict__ C, int nrows) {
    extern __shared__ float sm[];
    float* As = sm;               // [128][132] padded
    float* Bs = sm + 128 * 132;   // [128][128]
    const int m0 = blockIdx.x * 128;
    const int tid = threadIdx.x;

#pragma unroll
    for (int it = 0; it < 16; it++) {
        int idx = tid + it * 256;       // float4 index, 0..4095
        int row = idx >> 5;
        int c4 = (idx & 31) << 2;
        float4 va = make_float4(0.f, 0.f, 0.f, 0.f);
        if (m0 + row < nrows) va = *(const float4*)&A[(size_t)(m0 + row) * Fd + c4];
        *(float4*)&As[row * 132 + c4] = va;
        *(float4*)&Bs[row * 128 + c4] = *(const float4*)&B[row * Fd + c4];
    }
    __syncthreads();

    const int ty = tid >> 4;   // 0..15 -> rows ty*8..ty*8+7
    const int tx = tid & 15;   // cols tx*4..tx*4+3 and 64+tx*4..64+tx*4+3

    unsigned long long acc[8][4];
#pragma unroll
    for (int i = 0; i < 8; i++)
#pragma unroll
        for (int j = 0; j < 4; j++) acc[i][j] = 0ull;

#pragma unroll 4
    for (int k = 0; k < 128; k++) {
        float4 b0 = *(const float4*)&Bs[k * 128 + tx * 4];
        float4 b1 = *(const float4*)&Bs[k * 128 + 64 + tx * 4];
        unsigned long long bp0 = pack2(b0.x, b0.y);
        unsigned long long bp1 = pack2(b0.z, b0.w);
        unsigned long long bp2 = pack2(b1.x, b1.y);
        unsigned long long bp3 = pack2(b1.z, b1.w);
#pragma unroll
        for (int i = 0; i < 8; i++) {
            float a = As[(ty * 8 + i) * 132 + k];
            unsigned long long ap = pack2(a, a);
            fma2(acc[i][0], ap, bp0);
            fma2(acc[i][1], ap, bp1);
            fma2(acc[i][2], ap, bp2);
            fma2(acc[i][3], ap, bp3);
        }
    }

#pragma unroll
    for (int i = 0; i < 8; i++) {
        int row = m0 + ty * 8 + i;
        if (row < nrows) {
            float2 v0 = unpack2(acc[i][0]);
            float2 v1 = unpack2(acc[i][1]);
            float2 v2 = unpack2(acc[i][2]);
            float2 v3 = unpack2(acc[i][3]);
            *(float4*)&C[(size_t)row * Fd + tx * 4] = make_float4(v0.x, v0.y, v1.x, v1.y);
            *(float4*)&C[(size_t)row * Fd + 64 + tx * 4] = make_float4(v2.x, v2.y, v3.x, v3.y);
        }
    }
}

// ---------------- per-node attention scores: el/er[n,h] = dot(f[n,h,:], al/ar[h,:]) ----------------
__global__ void __launch_bounds__(256) scores_k(const float* __restrict__ f,
                                                const float* __restrict__ al,
                                                const float* __restrict__ ar,
                                                float* __restrict__ el,
                                                float* __restrict__ er) {
    int w = (int)(((size_t)blockIdx.x * blockDim.x + threadIdx.x) >> 5);
    if (w >= Nn) return;
    int lane = threadIdx.x & 31;
    float4 fv = *(const float4*)&f[(size_t)w * Fd + lane * 4];
    float4 av = *(const float4*)&al[lane * 4];
    float4 rv = *(const float4*)&ar[lane * 4];
    float pel = fv.x * av.x + fv.y * av.y + fv.z * av.z + fv.w * av.w;
    float per = fv.x * rv.x + fv.y * rv.y + fv.z * rv.z + fv.w * rv.w;
#pragma unroll
    for (int off = 8; off; off >>= 1) {
        pel += __shfl_down_sync(0xffffffffu, pel, off, 16);
        per += __shfl_down_sync(0xffffffffu, per, off, 16);
    }
    if ((lane & 15) == 0) {
        int h = lane >> 4;
        el[w * NH + h] = pel;
        er[w * NH + h] = per;
    }
}

// ---------------- edge pass: one warp per edge ----------------
// Softmax shift-invariance => skip segment-max (scores are O(1), no overflow).
// Normalization factors out => accumulate unnormalized: agg[dst] += f[src]*exp(e),
// s[dst] += exp(e). Vector RED (no return) for the 128-float scatter.
__global__ void __launch_bounds__(256) edge_k(const int* __restrict__ src,
                                              const int* __restrict__ dst,
                                              const float* __restrict__ el,
                                              const float* __restrict__ er,
                                              const float* __restrict__ f,
                                              float* __restrict__ agg,
                                              float* __restrict__ s) {
    long long gw = ((long long)blockIdx.x * blockDim.x + threadIdx.x) >> 5;
    if (gw >= Ee) return;
    int lane = threadIdx.x & 31;
    int u = __ldg(&src[gw]);
    int v = __ldg(&dst[gw]);
    int h = lane >> 4;
    float e = __ldg(&el[u * NH + h]) + __ldg(&er[v * NH + h]);
    e = (e > 0.f) ? e : 0.2f * e;           // leaky_relu(0.2)
    float w = __expf(e);
    if ((lane & 15) == 0) atomicAdd(&s[v * NH + h], w);
    float4 fv = *(const float4*)&f[(size_t)u * Fd + lane * 4];
    float* p = &agg[(size_t)v * Fd + lane * 4];
    asm volatile("red.global.add.v4.f32 [%0], {%1, %2, %3, %4};" ::"l"(p),
                 "f"(fv.x * w), "f"(fv.y * w), "f"(fv.z * w), "f"(fv.w * w)
                 : "memory");
}

// ---------------- epilogue: hout += elu(agg/s + b) ----------------
__global__ void __launch_bounds__(256) epi_k(const float* __restrict__ agg,
                                             const float* __restrict__ s,
                                             const float* __restrict__ b,
                                             float* __restrict__ hout) {
    int i = blockIdx.x * blockDim.x + threadIdx.x;
    if (i >= Nn * Fd) return;
    int n = i >> 7;
    int c = i & 127;
    int h = c >> 6;
    float sv = s[n * NH + h];
    float v = (sv > 0.f) ? agg[i] / sv : 0.f;  // nodes w/o in-edges: agg term is 0
    v += b[c];
    hout[i] += (v > 0.f) ? v : expm1f(v);      // elu, alpha=1
}

// ---------------- layer driver ----------------
static void run_layer(const float* hin, const float* W, const float* al,
                      const float* ar, const float* b, const int* src,
                      const int* dst, float* hout, float* f, float* agg,
                      float* el, float* er, float* s) {
    cudaMemsetAsync(hout, 0, (size_t)Nn * Fd * sizeof(float));
    for (int r = 0; r < 2; r++) {
        gemm_k<<<(Nn + 127) / 128, 256, GEMM_SMEM>>>(hin, W + (size_t)r * Fd * Fd, f, Nn);
        scores_k<<<(Nn * 32 + 255) / 256, 256>>>(f, al + r * Fd, ar + r * Fd, el, er);
        cudaMemsetAsync(agg, 0, (size_t)Nn * Fd * sizeof(float));
        cudaMemsetAsync(s, 0, (size_t)Nn * NH * sizeof(float));
        edge_k<<<(int)(((long long)Ee * 32) / 256), 256>>>(
            src + (size_t)r * Ee, dst + (size_t)r * Ee, el, er, f, agg, s);
        epi_k<<<(Nn * Fd + 255) / 256, 256>>>(agg, s, b + r * Fd, hout);
    }
}

extern "C" void kernel_launch(void* const* d_in, const int* in_sizes, int n_in,
                              void* d_out, int out_size) {
    const float* x   = (const float*)d_in[0];
    const float* W0  = (const float*)d_in[1];
    const float* al0 = (const float*)d_in[2];
    const float* ar0 = (const float*)d_in[3];
    const float* b0  = (const float*)d_in[4];
    const float* W1  = (const float*)d_in[5];
    const float* al1 = (const float*)d_in[6];
    const float* ar1 = (const float*)d_in[7];
    const float* b1  = (const float*)d_in[8];
    const int* src0  = (const int*)d_in[9];
    const int* dst0  = (const int*)d_in[10];
    const int* src1  = (const int*)d_in[11];
    const int* dst1  = (const int*)d_in[12];
    float* out = (float*)d_out;

    float *f, *agg, *h1, *el, *er, *s;
    cudaGetSymbolAddress((void**)&f, g_f);
    cudaGetSymbolAddress((void**)&agg, g_agg);
    cudaGetSymbolAddress((void**)&h1, g_h1);
    cudaGetSymbolAddress((void**)&el, g_el);
    cudaGetSymbolAddress((void**)&er, g_er);
    cudaGetSymbolAddress((void**)&s, g_s);

    cudaFuncSetAttribute(gemm_k, cudaFuncAttributeMaxDynamicSharedMemorySize,
                         GEMM_SMEM);

    run_layer(x, W0, al0, ar0, b0, src0, dst0, h1, f, agg, el, er, s);
    run_layer(h1, W1, al1, ar1, b1, src1, dst1, out, f, agg, el, er, s);
}